// round 2
// baseline (speedup 1.0000x reference)
#include <cuda_runtime.h>
#include <math.h>

#define DIM   4096
#define NH    32
#define NKV   8
#define G     4
#define HD    128
#define INTER 14336
#define PS    16
#define B     32
#define QKV_M ((NH + 2*NKV) * HD)   // 6144
#define EPS   1e-5f
#define SCALE 0.08838834764831845f  // 1/sqrt(128)

#define SPLIT 4      // attention split-KV
#define SQKV  4      // split-K for qkv GEMM  (K=4096 -> 1024)
#define SWO   4      // split-K for wo GEMM   (K=4096 -> 1024)
#define SW1   2      // split-K for w1 GEMM   (K=4096 -> 2048)
#define SW2   7      // split-K for w2 GEMM   (K=14336 -> 2048)

// ------------------------- device scratch -------------------------
__device__ float g_xaT [DIM * B];                  // rmsnorm(x)^T  [k][b]
__device__ float g_qkvP[SQKV * QKV_M * B];         // qkv partials  [s][m][b]
__device__ float g_q   [B * NH * HD];              // roped q (pre-scaled)
__device__ float g_kn  [B * NKV * HD];             // roped k_new
__device__ float g_vn  [B * NKV * HD];             // v_new
__device__ float g_pO  [B * NKV * SPLIT * G * HD]; // attn partial O
__device__ float g_pML [B * NKV * SPLIT * G * 2];  // attn partial (m, l)
__device__ float g_oT  [NH * HD * B];              // attn out^T    [k][b]
__device__ float g_woP [SWO * DIM * B];
__device__ float g_hT  [DIM * B];                  // h^T
__device__ float g_hfT [DIM * B];                  // rmsnorm(h)^T
__device__ float g_w1P [SW1 * INTER * B];
__device__ float g_gT  [INTER * B];                // (silu*stem)^T
__device__ float g_w2P [SW2 * DIM * B];

// ------------------------- f32x2 helpers -------------------------
__device__ __forceinline__ unsigned long long pk2(float a, float b) {
    unsigned long long r;
    asm("mov.b64 %0, {%1, %2};" : "=l"(r) : "f"(a), "f"(b));
    return r;
}
__device__ __forceinline__ void fma2(unsigned long long &d,
                                     unsigned long long a,
                                     unsigned long long b) {
    asm("fma.rn.f32x2 %0, %1, %2, %3;" : "=l"(d) : "l"(a), "l"(b), "l"(d));
}
__device__ __forceinline__ void upk2(unsigned long long v, float &a, float &b) {
    asm("mov.b64 {%0, %1}, %2;" : "=f"(a), "=f"(b) : "l"(v));
}

// ------------------------- block reduce (256 threads) -------------------------
__device__ __forceinline__ float blockReduceSum256(float v) {
    __shared__ float sh[8];
    int lane = threadIdx.x & 31, w = threadIdx.x >> 5;
    #pragma unroll
    for (int o = 16; o; o >>= 1) v += __shfl_xor_sync(0xffffffffu, v, o);
    if (lane == 0) sh[w] = v;
    __syncthreads();
    if (threadIdx.x == 0) {
        float total = sh[0];
        #pragma unroll
        for (int i = 1; i < 8; i++) total += sh[i];
        sh[0] = total;
    }
    __syncthreads();
    float total = sh[0];
    __syncthreads();
    return total;
}

// ------------------------- kernel 1: rmsnorm(x) -> xaT -------------------------
__global__ __launch_bounds__(256) void k_rms_x(const float* __restrict__ x,
                                               const float* __restrict__ w) {
    int b = blockIdx.x, tid = threadIdx.x;
    float v[16];
    float ss = 0.f;
    #pragma unroll
    for (int i = 0; i < 16; i++) {
        float t = x[b * DIM + tid + i * 256];
        v[i] = t; ss += t * t;
    }
    ss = blockReduceSum256(ss);
    float r = rsqrtf(ss / (float)DIM + EPS);
    #pragma unroll
    for (int i = 0; i < 16; i++) {
        int m = tid + i * 256;
        g_xaT[m * B + b] = v[i] * r * w[m];
    }
}

// ------------------------- generic split-K GEMM -------------------------
// P[s][m][b] = sum_{k in split s} W[m][k] * XT[k][b]
// BM=64, BK=32, N=B=32, 128 threads, thread tile 4m x 4n via f32x2 FMA.
__global__ __launch_bounds__(128) void k_gemm(const float* __restrict__ W,
                                              const float* __restrict__ XT,
                                              float* __restrict__ P,
                                              int M, int K, int kps) {
    __shared__ float Ws[64][33];
    __shared__ float Xs[32][32];
    const int tid = threadIdx.x;
    const int tx = tid & 7, ty = tid >> 3;
    const int m0 = blockIdx.x * 64;
    const int kb = blockIdx.y * kps;
    const int ke = min(K, kb + kps);

    unsigned long long acc[4][2];
    #pragma unroll
    for (int j = 0; j < 4; j++) { acc[j][0] = 0ull; acc[j][1] = 0ull; }

    for (int k0 = kb; k0 < ke; k0 += 32) {
        #pragma unroll
        for (int i = 0; i < 4; i++) {
            int idx = i * 128 + tid;
            int r = idx >> 3, c4 = idx & 7;
            float4 w4 = *(const float4*)(W + (size_t)(m0 + r) * K + k0 + c4 * 4);
            Ws[r][c4 * 4 + 0] = w4.x; Ws[r][c4 * 4 + 1] = w4.y;
            Ws[r][c4 * 4 + 2] = w4.z; Ws[r][c4 * 4 + 3] = w4.w;
        }
        #pragma unroll
        for (int i = 0; i < 2; i++) {
            int idx = i * 128 + tid;
            int r = idx >> 3, c4 = idx & 7;
            *(float4*)&Xs[r][c4 * 4] =
                *(const float4*)(XT + (size_t)(k0 + r) * B + c4 * 4);
        }
        __syncthreads();
        #pragma unroll 8
        for (int kk = 0; kk < 32; ++kk) {
            float4 xv = *(const float4*)&Xs[kk][tx * 4];
            unsigned long long xb0 = pk2(xv.x, xv.y);
            unsigned long long xb1 = pk2(xv.z, xv.w);
            #pragma unroll
            for (int j = 0; j < 4; j++) {
                float wv = Ws[ty * 4 + j][kk];
                unsigned long long wd = pk2(wv, wv);
                fma2(acc[j][0], wd, xb0);
                fma2(acc[j][1], wd, xb1);
            }
        }
        __syncthreads();
    }
    #pragma unroll
    for (int j = 0; j < 4; j++) {
        float a0, a1, a2, a3;
        upk2(acc[j][0], a0, a1);
        upk2(acc[j][1], a2, a3);
        size_t base = ((size_t)blockIdx.y * M + (m0 + ty * 4 + j)) * B + tx * 4;
        P[base + 0] = a0; P[base + 1] = a1; P[base + 2] = a2; P[base + 3] = a3;
    }
}

// ------------------------- kernel 3: combine qkv partials + rope -------------------------
__global__ __launch_bounds__(128) void k_rope(const int* __restrict__ offsets) {
    int b = blockIdx.x, hh = blockIdx.y, d = threadIdx.x;
    __shared__ float sm[HD];
    int m = hh * HD + d;
    float v = 0.f;
    #pragma unroll
    for (int s = 0; s < SQKV; s++)
        v += g_qkvP[(size_t)s * QKV_M * B + (size_t)m * B + b];
    sm[d] = v;
    __syncthreads();
    if (hh < NH + NKV) {
        int j = (d & 63);
        double inv = exp(-((double)j / 64.0) * log(10000.0));
        double ang = (double)offsets[b] * inv;
        double si, co;
        sincos(ang, &si, &co);
        float out;
        if (d < 64) out = sm[d] * (float)co - sm[d + 64] * (float)si;
        else        out = sm[d - 64] * (float)si + sm[d] * (float)co;
        if (hh < NH)
            g_q[(size_t)b * NH * HD + hh * HD + d] = out * SCALE;
        else
            g_kn[(size_t)b * NKV * HD + (hh - NH) * HD + d] = out;
    } else {
        g_vn[(size_t)b * NKV * HD + (hh - NH - NKV) * HD + d] = v;
    }
}

// ------------------------- kernel 4: flash attention, split-KV -------------------------
__global__ __launch_bounds__(128) void k_attn(const float* __restrict__ pk,
                                              const float* __restrict__ pv,
                                              const int* __restrict__ pidx,
                                              const int* __restrict__ pindptr,
                                              const int* __restrict__ plast) {
    int s = blockIdx.x, kvh = blockIdx.y, b = blockIdx.z;
    int tid = threadIdx.x, w = tid >> 5, lane = tid & 31;
    __shared__ float smq[G * HD];
    __shared__ float so[4][G][HD];
    __shared__ float sml[4][G][2];

    for (int i = tid; i < G * HD; i += 128)
        smq[i] = g_q[(size_t)b * NH * HD + (kvh * G) * HD + i];
    __syncthreads();
    float4 q[G];
    #pragma unroll
    for (int h = 0; h < G; h++) q[h] = *(float4*)&smq[h * HD + lane * 4];

    int p0 = pindptr[b];
    int npages = pindptr[b + 1] - p0;
    int kvlen = (npages - 1) * PS + plast[b];
    int chunk = (kvlen + SPLIT - 1) / SPLIT;
    int cs = s * chunk, ce = min(cs + chunk, kvlen);

    float mv[G], lv[G];
    float4 o[G];
    #pragma unroll
    for (int h = 0; h < G; h++) {
        mv[h] = -1e30f; lv[h] = 0.f; o[h] = make_float4(0.f, 0.f, 0.f, 0.f);
    }

    for (int pos = cs + w; pos < ce; pos += 4) {
        const float *kp, *vp;
        if (pos == kvlen - 1) {
            kp = g_kn + ((size_t)b * NKV + kvh) * HD;
            vp = g_vn + ((size_t)b * NKV + kvh) * HD;
        } else {
            int pg = pidx[p0 + (pos >> 4)];
            size_t base = (((size_t)pg * PS + (pos & 15)) * NKV + kvh) * HD;
            kp = pk + base;
            vp = pv + base;
        }
        float4 k4 = *(const float4*)(kp + lane * 4);
        float4 v4 = *(const float4*)(vp + lane * 4);
        float sc[G];
        #pragma unroll
        for (int h = 0; h < G; h++)
            sc[h] = q[h].x * k4.x + q[h].y * k4.y + q[h].z * k4.z + q[h].w * k4.w;
        #pragma unroll
        for (int off = 16; off; off >>= 1) {
            #pragma unroll
            for (int h = 0; h < G; h++)
                sc[h] += __shfl_xor_sync(0xffffffffu, sc[h], off);
        }
        #pragma unroll
        for (int h = 0; h < G; h++) {
            float mn = fmaxf(mv[h], sc[h]);
            float corr = __expf(mv[h] - mn);
            float p = __expf(sc[h] - mn);
            lv[h] = lv[h] * corr + p;
            o[h].x = o[h].x * corr + p * v4.x;
            o[h].y = o[h].y * corr + p * v4.y;
            o[h].z = o[h].z * corr + p * v4.z;
            o[h].w = o[h].w * corr + p * v4.w;
            mv[h] = mn;
        }
    }

    #pragma unroll
    for (int h = 0; h < G; h++) {
        so[w][h][lane * 4 + 0] = o[h].x;
        so[w][h][lane * 4 + 1] = o[h].y;
        so[w][h][lane * 4 + 2] = o[h].z;
        so[w][h][lane * 4 + 3] = o[h].w;
        if (lane == 0) { sml[w][h][0] = mv[h]; sml[w][h][1] = lv[h]; }
    }
    __syncthreads();

    size_t pbase = (size_t)(b * NKV + kvh) * SPLIT + s;
    for (int h = 0; h < G; h++) {
        float M = -1e30f;
        #pragma unroll
        for (int ww = 0; ww < 4; ww++) M = fmaxf(M, sml[ww][h][0]);
        float L = 0.f, Od = 0.f;
        #pragma unroll
        for (int ww = 0; ww < 4; ww++) {
            float f = __expf(sml[ww][h][0] - M);
            L += sml[ww][h][1] * f;
            Od += so[ww][h][tid] * f;
        }
        g_pO[(pbase * G + h) * HD + tid] = Od;
        if (tid == 0) {
            g_pML[(pbase * G + h) * 2 + 0] = M;
            g_pML[(pbase * G + h) * 2 + 1] = L;
        }
    }
}

// ------------------------- kernel 5: combine attention splits -> oT -------------------------
__global__ __launch_bounds__(128) void k_attn_comb() {
    int hh = blockIdx.x, b = blockIdx.y, d = threadIdx.x;
    int kvh = hh >> 2, h = hh & 3;
    size_t base0 = (size_t)(b * NKV + kvh) * SPLIT;
    float M = -1e30f;
    #pragma unroll
    for (int s = 0; s < SPLIT; s++)
        M = fmaxf(M, g_pML[((base0 + s) * G + h) * 2]);
    float L = 0.f, Od = 0.f;
    #pragma unroll
    for (int s = 0; s < SPLIT; s++) {
        float f = __expf(g_pML[((base0 + s) * G + h) * 2] - M);
        L += g_pML[((base0 + s) * G + h) * 2 + 1] * f;
        Od += g_pO[((base0 + s) * G + h) * HD + d] * f;
    }
    g_oT[(size_t)(hh * HD + d) * B + b] = Od / L;
}

// ------------------------- kernel 7: h = x + woP; hfT = rmsnorm(h) -------------------------
__global__ __launch_bounds__(256) void k_resid1(const float* __restrict__ x,
                                                const float* __restrict__ fw) {
    int b = blockIdx.x, tid = threadIdx.x;
    float hv[16];
    float ss = 0.f;
    #pragma unroll
    for (int i = 0; i < 16; i++) {
        int m = tid + i * 256;
        float t = x[b * DIM + m];
        #pragma unroll
        for (int s = 0; s < SWO; s++)
            t += g_woP[(size_t)s * DIM * B + (size_t)m * B + b];
        hv[i] = t; ss += t * t;
        g_hT[(size_t)m * B + b] = t;
    }
    ss = blockReduceSum256(ss);
    float r = rsqrtf(ss / (float)DIM + EPS);
    #pragma unroll
    for (int i = 0; i < 16; i++) {
        int m = tid + i * 256;
        g_hfT[(size_t)m * B + b] = hv[i] * r * fw[m];
    }
}

// ------------------------- kernel 9: silu(w1P) * stem -> gT -------------------------
__global__ __launch_bounds__(256) void k_silu(const float* __restrict__ buffer,
                                              const int* __restrict__ bids) {
    int idx = blockIdx.x * 256 + threadIdx.x;   // idx = m*B + b
    int b = idx & 31, m = idx >> 5;
    float v = 0.f;
    #pragma unroll
    for (int s = 0; s < SW1; s++)
        v += g_w1P[(size_t)s * INTER * B + idx];
    float sig = 1.f / (1.f + expf(-v));
    float stem = buffer[(size_t)bids[b] * INTER + m];
    g_gT[idx] = v * sig * stem;
}

// ------------------------- kernel 11: out = h + w2P -------------------------
__global__ __launch_bounds__(256) void k_final(float* __restrict__ out) {
    int idx = blockIdx.x * 256 + threadIdx.x;   // idx = b*DIM + m
    int b = idx >> 12, m = idx & 4095;
    float v = g_hT[(size_t)m * B + b];
    #pragma unroll
    for (int s = 0; s < SW2; s++)
        v += g_w2P[(size_t)s * DIM * B + (size_t)m * B + b];
    out[idx] = v;
}

// ------------------------- launch -------------------------
extern "C" void kernel_launch(void* const* d_in, const int* in_sizes, int n_in,
                              void* d_out, int out_size) {
    (void)in_sizes; (void)n_in; (void)out_size;
    const float* x        = (const float*)d_in[0];
    const float* buffer   = (const float*)d_in[1];
    const float* paged_k  = (const float*)d_in[2];
    const float* paged_v  = (const float*)d_in[3];
    const float* wqkv     = (const float*)d_in[4];
    const float* wo       = (const float*)d_in[5];
    const float* w1       = (const float*)d_in[6];
    const float* w2       = (const float*)d_in[7];
    const float* attn_w   = (const float*)d_in[8];
    const float* ffn_w    = (const float*)d_in[9];
    const int*   bids     = (const int*)d_in[10];
    const int*   offsets  = (const int*)d_in[11];
    const int*   pidx     = (const int*)d_in[13];
    const int*   pindptr  = (const int*)d_in[14];
    const int*   plast    = (const int*)d_in[15];
    float* out = (float*)d_out;

    float* xaT;  cudaGetSymbolAddress((void**)&xaT,  g_xaT);
    float* qkvP; cudaGetSymbolAddress((void**)&qkvP, g_qkvP);
    float* oT;   cudaGetSymbolAddress((void**)&oT,   g_oT);
    float* woP;  cudaGetSymbolAddress((void**)&woP,  g_woP);
    float* hfT;  cudaGetSymbolAddress((void**)&hfT,  g_hfT);
    float* w1P;  cudaGetSymbolAddress((void**)&w1P,  g_w1P);
    float* gT;   cudaGetSymbolAddress((void**)&gT,   g_gT);
    float* w2P;  cudaGetSymbolAddress((void**)&w2P,  g_w2P);

    k_rms_x<<<B, 256>>>(x, attn_w);
    k_gemm<<<dim3(QKV_M / 64, SQKV), 128>>>(wqkv, xaT, qkvP, QKV_M, DIM, DIM / SQKV);
    k_rope<<<dim3(B, 48), 128>>>(offsets);
    k_attn<<<dim3(SPLIT, NKV, B), 128>>>(paged_k, paged_v, pidx, pindptr, plast);
    k_attn_comb<<<dim3(NH, B), 128>>>();
    k_gemm<<<dim3(DIM / 64, SWO), 128>>>(wo, oT, woP, DIM, NH * HD, (NH * HD) / SWO);
    k_resid1<<<B, 256>>>(x, ffn_w);
    k_gemm<<<dim3(INTER / 64, SW1), 128>>>(w1, hfT, w1P, INTER, DIM, DIM / SW1);
    k_silu<<<(INTER * B) / 256, 256>>>(buffer, bids);
    k_gemm<<<dim3(DIM / 64, SW2), 128>>>(w2, gT, w2P, DIM, INTER, INTER / SW2);
    k_final<<<(B * DIM) / 256, 256>>>(out);
}

// round 3
// speedup vs baseline: 1.0987x; 1.0987x over previous
#include <cuda_runtime.h>
#include <math.h>

#define DIM   4096
#define NH    32
#define NKV   8
#define G     4
#define HD    128
#define INTER 14336
#define PS    16
#define B     32
#define QKV_M ((NH + 2*NKV) * HD)   // 6144
#define EPS   1e-5f
#define SCALE 0.08838834764831845f  // 1/sqrt(128)

#define SPLIT 4      // attention split-KV
#define SQKV  8      // split-K for qkv GEMM  (K=4096 -> 512)
#define SWO   8      // split-K for wo GEMM   (K=4096 -> 512)
#define SW1   4      // split-K for w1 GEMM   (K=4096 -> 1024)
#define SW2   8      // split-K for w2 GEMM   (K=14336 -> 1792)

// ------------------------- device scratch -------------------------
__device__ float g_xaT [DIM * B];                  // rmsnorm(x)^T  [k][b]
__device__ float g_qkvP[SQKV * QKV_M * B];         // qkv partials  [s][m][b]
__device__ float g_q   [B * NH * HD];              // roped q (pre-scaled)
__device__ float g_kn  [B * NKV * HD];             // roped k_new
__device__ float g_vn  [B * NKV * HD];             // v_new
__device__ float g_pO  [B * NKV * SPLIT * G * HD]; // attn partial O
__device__ float g_pML [B * NKV * SPLIT * G * 2];  // attn partial (m, l)
__device__ float g_oT  [NH * HD * B];              // attn out^T    [k][b]
__device__ float g_woP [SWO * DIM * B];
__device__ float g_hT  [DIM * B];                  // h^T
__device__ float g_hfT [DIM * B];                  // rmsnorm(h)^T
__device__ float g_w1P [SW1 * INTER * B];
__device__ float g_gT  [INTER * B];                // (silu*stem)^T
__device__ float g_w2P [SW2 * DIM * B];

// ------------------------- f32x2 helpers -------------------------
__device__ __forceinline__ unsigned long long pk2(float a, float b) {
    unsigned long long r;
    asm("mov.b64 %0, {%1, %2};" : "=l"(r) : "f"(a), "f"(b));
    return r;
}
__device__ __forceinline__ void fma2(unsigned long long &d,
                                     unsigned long long a,
                                     unsigned long long b) {
    asm("fma.rn.f32x2 %0, %1, %2, %3;" : "=l"(d) : "l"(a), "l"(b), "l"(d));
}
__device__ __forceinline__ void upk2(unsigned long long v, float &a, float &b) {
    asm("mov.b64 {%0, %1}, %2;" : "=f"(a), "=f"(b) : "l"(v));
}

// ------------------------- block reduce (256 threads) -------------------------
__device__ __forceinline__ float blockReduceSum256(float v) {
    __shared__ float sh[8];
    int lane = threadIdx.x & 31, w = threadIdx.x >> 5;
    #pragma unroll
    for (int o = 16; o; o >>= 1) v += __shfl_xor_sync(0xffffffffu, v, o);
    if (lane == 0) sh[w] = v;
    __syncthreads();
    if (threadIdx.x == 0) {
        float total = sh[0];
        #pragma unroll
        for (int i = 1; i < 8; i++) total += sh[i];
        sh[0] = total;
    }
    __syncthreads();
    float total = sh[0];
    __syncthreads();
    return total;
}

// ------------------------- kernel 1: rmsnorm(x) -> xaT -------------------------
__global__ __launch_bounds__(256) void k_rms_x(const float* __restrict__ x,
                                               const float* __restrict__ w) {
    int b = blockIdx.x, tid = threadIdx.x;
    float v[16];
    float ss = 0.f;
    #pragma unroll
    for (int i = 0; i < 16; i++) {
        float t = x[b * DIM + tid + i * 256];
        v[i] = t; ss += t * t;
    }
    ss = blockReduceSum256(ss);
    float r = rsqrtf(ss / (float)DIM + EPS);
    #pragma unroll
    for (int i = 0; i < 16; i++) {
        int m = tid + i * 256;
        g_xaT[m * B + b] = v[i] * r * w[m];
    }
}

// ------------------------- generic split-K GEMM -------------------------
// P[s][m][b] = sum_{k in split s} W[m][k] * XT[k][b]
// BM=128, BK=16, N=B=32, 128 threads.
// Per-thread tile: 8 m (4 m-pairs via LDS.64 of transposed W) x 4 n, f32x2 FMA.
__global__ __launch_bounds__(128) void k_gemm(const float* __restrict__ W,
                                              const float* __restrict__ XT,
                                              float* __restrict__ P,
                                              int M, int K, int kps) {
    __shared__ float Ws[16][130];   // [k][m], row stride 130 (8B-aligned rows)
    __shared__ float Xs[16][32];    // [k][n]
    const int tid = threadIdx.x;
    const int tx = tid & 7;         // n quad: n = tx*4 .. tx*4+3
    const int ty = tid >> 3;        // m group: m = ty*8 .. ty*8+7
    const int m0 = blockIdx.x * 128;
    const int kb = blockIdx.y * kps;
    const int ke = kb + kps;

    unsigned long long acc[4][4];
    #pragma unroll
    for (int p = 0; p < 4; p++)
        #pragma unroll
        for (int j = 0; j < 4; j++) acc[p][j] = 0ull;

    const int xr = tid >> 3, xc = (tid & 7) * 4;

    for (int k0 = kb; k0 < ke; k0 += 16) {
        // load W tile 128x16, store transposed
        #pragma unroll
        for (int i = 0; i < 4; i++) {
            int idx = i * 128 + tid;
            int r = idx >> 2, c4 = idx & 3;
            float4 w4 = *(const float4*)(W + (size_t)(m0 + r) * K + k0 + c4 * 4);
            Ws[c4 * 4 + 0][r] = w4.x;
            Ws[c4 * 4 + 1][r] = w4.y;
            Ws[c4 * 4 + 2][r] = w4.z;
            Ws[c4 * 4 + 3][r] = w4.w;
        }
        // load X tile 16x32
        *(float4*)&Xs[xr][xc] = *(const float4*)(XT + (size_t)(k0 + xr) * B + xc);
        __syncthreads();

        #pragma unroll
        for (int kk = 0; kk < 16; ++kk) {
            float4 xv = *(const float4*)&Xs[kk][tx * 4];
            unsigned long long xx0 = pk2(xv.x, xv.x);
            unsigned long long xx1 = pk2(xv.y, xv.y);
            unsigned long long xx2 = pk2(xv.z, xv.z);
            unsigned long long xx3 = pk2(xv.w, xv.w);
            unsigned long long wp[4];
            #pragma unroll
            for (int p = 0; p < 4; p++)
                wp[p] = *(const unsigned long long*)&Ws[kk][ty * 8 + p * 2];
            #pragma unroll
            for (int p = 0; p < 4; p++) {
                fma2(acc[p][0], wp[p], xx0);
                fma2(acc[p][1], wp[p], xx1);
                fma2(acc[p][2], wp[p], xx2);
                fma2(acc[p][3], wp[p], xx3);
            }
        }
        __syncthreads();
    }

    // epilogue: m = m0 + ty*8 + p*2 + e, n = tx*4 + j
    #pragma unroll
    for (int p = 0; p < 4; p++) {
        float lo[4], hi[4];
        #pragma unroll
        for (int j = 0; j < 4; j++) upk2(acc[p][j], lo[j], hi[j]);
        size_t mE = (size_t)m0 + ty * 8 + p * 2;
        size_t base = ((size_t)blockIdx.y * M + mE) * B + tx * 4;
        *(float4*)&P[base]     = make_float4(lo[0], lo[1], lo[2], lo[3]);
        *(float4*)&P[base + B] = make_float4(hi[0], hi[1], hi[2], hi[3]);
    }
}

// ------------------------- kernel 3: combine qkv partials + rope -------------------------
__global__ __launch_bounds__(128) void k_rope(const int* __restrict__ offsets) {
    int b = blockIdx.x, hh = blockIdx.y, d = threadIdx.x;
    __shared__ float sm[HD];
    int m = hh * HD + d;
    float v = 0.f;
    #pragma unroll
    for (int s = 0; s < SQKV; s++)
        v += g_qkvP[(size_t)s * QKV_M * B + (size_t)m * B + b];
    sm[d] = v;
    __syncthreads();
    if (hh < NH + NKV) {
        int j = (d & 63);
        double inv = exp(-((double)j / 64.0) * log(10000.0));
        double ang = (double)offsets[b] * inv;
        double si, co;
        sincos(ang, &si, &co);
        float out;
        if (d < 64) out = sm[d] * (float)co - sm[d + 64] * (float)si;
        else        out = sm[d - 64] * (float)si + sm[d] * (float)co;
        if (hh < NH)
            g_q[(size_t)b * NH * HD + hh * HD + d] = out * SCALE;
        else
            g_kn[(size_t)b * NKV * HD + (hh - NH) * HD + d] = out;
    } else {
        g_vn[(size_t)b * NKV * HD + (hh - NH - NKV) * HD + d] = v;
    }
}

// ------------------------- kernel 4: flash attention, split-KV -------------------------
__global__ __launch_bounds__(128) void k_attn(const float* __restrict__ pk,
                                              const float* __restrict__ pv,
                                              const int* __restrict__ pidx,
                                              const int* __restrict__ pindptr,
                                              const int* __restrict__ plast) {
    int s = blockIdx.x, kvh = blockIdx.y, b = blockIdx.z;
    int tid = threadIdx.x, w = tid >> 5, lane = tid & 31;
    __shared__ float smq[G * HD];
    __shared__ float so[4][G][HD];
    __shared__ float sml[4][G][2];

    for (int i = tid; i < G * HD; i += 128)
        smq[i] = g_q[(size_t)b * NH * HD + (kvh * G) * HD + i];
    __syncthreads();
    float4 q[G];
    #pragma unroll
    for (int h = 0; h < G; h++) q[h] = *(float4*)&smq[h * HD + lane * 4];

    int p0 = pindptr[b];
    int npages = pindptr[b + 1] - p0;
    int kvlen = (npages - 1) * PS + plast[b];
    int chunk = (kvlen + SPLIT - 1) / SPLIT;
    int cs = s * chunk, ce = min(cs + chunk, kvlen);
    int kvm1 = kvlen - 1;
    int ce2 = min(ce, kvm1);   // main loop excludes the appended token

    float mv[G], lv[G];
    float4 o[G];
    #pragma unroll
    for (int h = 0; h < G; h++) {
        mv[h] = -1e30f; lv[h] = 0.f; o[h] = make_float4(0.f, 0.f, 0.f, 0.f);
    }

    for (int pos = cs + w * 2; pos < ce2; pos += 8) {
        int pg0 = pidx[p0 + (pos >> 4)];
        size_t ba = (((size_t)pg0 * PS + (pos & 15)) * NKV + kvh) * HD;
        float4 k4a = *(const float4*)(pk + ba + lane * 4);
        float4 v4a = *(const float4*)(pv + ba + lane * 4);
        int pos1 = pos + 1;
        bool h1 = pos1 < ce2;                   // uniform across warp
        float4 k4b = make_float4(0.f, 0.f, 0.f, 0.f);
        float4 v4b = k4b;
        if (h1) {
            int pg1 = pidx[p0 + (pos1 >> 4)];
            size_t bb = (((size_t)pg1 * PS + (pos1 & 15)) * NKV + kvh) * HD;
            k4b = *(const float4*)(pk + bb + lane * 4);
            v4b = *(const float4*)(pv + bb + lane * 4);
        }
        float sa[G], sb[G];
        #pragma unroll
        for (int h = 0; h < G; h++) {
            sa[h] = q[h].x * k4a.x + q[h].y * k4a.y + q[h].z * k4a.z + q[h].w * k4a.w;
            sb[h] = q[h].x * k4b.x + q[h].y * k4b.y + q[h].z * k4b.z + q[h].w * k4b.w;
        }
        #pragma unroll
        for (int off = 16; off; off >>= 1) {
            #pragma unroll
            for (int h = 0; h < G; h++) {
                sa[h] += __shfl_xor_sync(0xffffffffu, sa[h], off);
                sb[h] += __shfl_xor_sync(0xffffffffu, sb[h], off);
            }
        }
        #pragma unroll
        for (int h = 0; h < G; h++) {
            float mn = fmaxf(mv[h], sa[h]);
            float corr = __expf(mv[h] - mn);
            float p = __expf(sa[h] - mn);
            lv[h] = lv[h] * corr + p;
            o[h].x = o[h].x * corr + p * v4a.x;
            o[h].y = o[h].y * corr + p * v4a.y;
            o[h].z = o[h].z * corr + p * v4a.z;
            o[h].w = o[h].w * corr + p * v4a.w;
            mv[h] = mn;
        }
        if (h1) {
            #pragma unroll
            for (int h = 0; h < G; h++) {
                float mn = fmaxf(mv[h], sb[h]);
                float corr = __expf(mv[h] - mn);
                float p = __expf(sb[h] - mn);
                lv[h] = lv[h] * corr + p;
                o[h].x = o[h].x * corr + p * v4b.x;
                o[h].y = o[h].y * corr + p * v4b.y;
                o[h].z = o[h].z * corr + p * v4b.z;
                o[h].w = o[h].w * corr + p * v4b.w;
                mv[h] = mn;
            }
        }
    }

    // appended token (always position kvlen-1): handled by warp 0 of owning split
    if (ce == kvlen && cs < kvlen && w == 0) {
        const float* kp = g_kn + ((size_t)b * NKV + kvh) * HD;
        const float* vp = g_vn + ((size_t)b * NKV + kvh) * HD;
        float4 k4 = *(const float4*)(kp + lane * 4);
        float4 v4 = *(const float4*)(vp + lane * 4);
        float sc[G];
        #pragma unroll
        for (int h = 0; h < G; h++)
            sc[h] = q[h].x * k4.x + q[h].y * k4.y + q[h].z * k4.z + q[h].w * k4.w;
        #pragma unroll
        for (int off = 16; off; off >>= 1)
            #pragma unroll
            for (int h = 0; h < G; h++)
                sc[h] += __shfl_xor_sync(0xffffffffu, sc[h], off);
        #pragma unroll
        for (int h = 0; h < G; h++) {
            float mn = fmaxf(mv[h], sc[h]);
            float corr = __expf(mv[h] - mn);
            float p = __expf(sc[h] - mn);
            lv[h] = lv[h] * corr + p;
            o[h].x = o[h].x * corr + p * v4.x;
            o[h].y = o[h].y * corr + p * v4.y;
            o[h].z = o[h].z * corr + p * v4.z;
            o[h].w = o[h].w * corr + p * v4.w;
            mv[h] = mn;
        }
    }

    #pragma unroll
    for (int h = 0; h < G; h++) {
        so[w][h][lane * 4 + 0] = o[h].x;
        so[w][h][lane * 4 + 1] = o[h].y;
        so[w][h][lane * 4 + 2] = o[h].z;
        so[w][h][lane * 4 + 3] = o[h].w;
        if (lane == 0) { sml[w][h][0] = mv[h]; sml[w][h][1] = lv[h]; }
    }
    __syncthreads();

    size_t pbase = (size_t)(b * NKV + kvh) * SPLIT + s;
    for (int h = 0; h < G; h++) {
        float M = -1e30f;
        #pragma unroll
        for (int ww = 0; ww < 4; ww++) M = fmaxf(M, sml[ww][h][0]);
        float L = 0.f, Od = 0.f;
        #pragma unroll
        for (int ww = 0; ww < 4; ww++) {
            float f = __expf(sml[ww][h][0] - M);
            L += sml[ww][h][1] * f;
            Od += so[ww][h][tid] * f;
        }
        g_pO[(pbase * G + h) * HD + tid] = Od;
        if (tid == 0) {
            g_pML[(pbase * G + h) * 2 + 0] = M;
            g_pML[(pbase * G + h) * 2 + 1] = L;
        }
    }
}

// ------------------------- kernel 5: combine attention splits -> oT -------------------------
__global__ __launch_bounds__(128) void k_attn_comb() {
    int hh = blockIdx.x, b = blockIdx.y, d = threadIdx.x;
    int kvh = hh >> 2, h = hh & 3;
    size_t base0 = (size_t)(b * NKV + kvh) * SPLIT;
    float M = -1e30f;
    #pragma unroll
    for (int s = 0; s < SPLIT; s++)
        M = fmaxf(M, g_pML[((base0 + s) * G + h) * 2]);
    float L = 0.f, Od = 0.f;
    #pragma unroll
    for (int s = 0; s < SPLIT; s++) {
        float f = __expf(g_pML[((base0 + s) * G + h) * 2] - M);
        L += g_pML[((base0 + s) * G + h) * 2 + 1] * f;
        Od += g_pO[((base0 + s) * G + h) * HD + d] * f;
    }
    g_oT[(size_t)(hh * HD + d) * B + b] = Od / L;
}

// ------------------------- kernel 7: h = x + woP; hfT = rmsnorm(h) -------------------------
__global__ __launch_bounds__(256) void k_resid1(const float* __restrict__ x,
                                                const float* __restrict__ fw) {
    int b = blockIdx.x, tid = threadIdx.x;
    float hv[16];
    float ss = 0.f;
    #pragma unroll
    for (int i = 0; i < 16; i++) {
        int m = tid + i * 256;
        float t = x[b * DIM + m];
        #pragma unroll
        for (int s = 0; s < SWO; s++)
            t += g_woP[(size_t)s * DIM * B + (size_t)m * B + b];
        hv[i] = t; ss += t * t;
        g_hT[(size_t)m * B + b] = t;
    }
    ss = blockReduceSum256(ss);
    float r = rsqrtf(ss / (float)DIM + EPS);
    #pragma unroll
    for (int i = 0; i < 16; i++) {
        int m = tid + i * 256;
        g_hfT[(size_t)m * B + b] = hv[i] * r * fw[m];
    }
}

// ------------------------- kernel 9: silu(w1P) * stem -> gT -------------------------
__global__ __launch_bounds__(256) void k_silu(const float* __restrict__ buffer,
                                              const int* __restrict__ bids) {
    int idx = blockIdx.x * 256 + threadIdx.x;   // idx = m*B + b
    int b = idx & 31, m = idx >> 5;
    float v = 0.f;
    #pragma unroll
    for (int s = 0; s < SW1; s++)
        v += g_w1P[(size_t)s * INTER * B + idx];
    float sig = 1.f / (1.f + expf(-v));
    float stem = buffer[(size_t)bids[b] * INTER + m];
    g_gT[idx] = v * sig * stem;
}

// ------------------------- kernel 11: out = h + w2P -------------------------
__global__ __launch_bounds__(256) void k_final(float* __restrict__ out) {
    int idx = blockIdx.x * 256 + threadIdx.x;   // idx = b*DIM + m
    int b = idx >> 12, m = idx & 4095;
    float v = g_hT[(size_t)m * B + b];
    #pragma unroll
    for (int s = 0; s < SW2; s++)
        v += g_w2P[(size_t)s * DIM * B + (size_t)m * B + b];
    out[idx] = v;
}

// ------------------------- launch -------------------------
extern "C" void kernel_launch(void* const* d_in, const int* in_sizes, int n_in,
                              void* d_out, int out_size) {
    (void)in_sizes; (void)n_in; (void)out_size;
    const float* x        = (const float*)d_in[0];
    const float* buffer   = (const float*)d_in[1];
    const float* paged_k  = (const float*)d_in[2];
    const float* paged_v  = (const float*)d_in[3];
    const float* wqkv     = (const float*)d_in[4];
    const float* wo       = (const float*)d_in[5];
    const float* w1       = (const float*)d_in[6];
    const float* w2       = (const float*)d_in[7];
    const float* attn_w   = (const float*)d_in[8];
    const float* ffn_w    = (const float*)d_in[9];
    const int*   bids     = (const int*)d_in[10];
    const int*   offsets  = (const int*)d_in[11];
    const int*   pidx     = (const int*)d_in[13];
    const int*   pindptr  = (const int*)d_in[14];
    const int*   plast    = (const int*)d_in[15];
    float* out = (float*)d_out;

    float* xaT;  cudaGetSymbolAddress((void**)&xaT,  g_xaT);
    float* qkvP; cudaGetSymbolAddress((void**)&qkvP, g_qkvP);
    float* oT;   cudaGetSymbolAddress((void**)&oT,   g_oT);
    float* woP;  cudaGetSymbolAddress((void**)&woP,  g_woP);
    float* hfT;  cudaGetSymbolAddress((void**)&hfT,  g_hfT);
    float* w1P;  cudaGetSymbolAddress((void**)&w1P,  g_w1P);
    float* gT;   cudaGetSymbolAddress((void**)&gT,   g_gT);
    float* w2P;  cudaGetSymbolAddress((void**)&w2P,  g_w2P);

    k_rms_x<<<B, 256>>>(x, attn_w);
    k_gemm<<<dim3(QKV_M / 128, SQKV), 128>>>(wqkv, xaT, qkvP, QKV_M, DIM, DIM / SQKV);
    k_rope<<<dim3(B, 48), 128>>>(offsets);
    k_attn<<<dim3(SPLIT, NKV, B), 128>>>(paged_k, paged_v, pidx, pindptr, plast);
    k_attn_comb<<<dim3(NH, B), 128>>>();
    k_gemm<<<dim3(DIM / 128, SWO), 128>>>(wo, oT, woP, DIM, NH * HD, (NH * HD) / SWO);
    k_resid1<<<B, 256>>>(x, ffn_w);
    k_gemm<<<dim3(INTER / 128, SW1), 128>>>(w1, hfT, w1P, INTER, DIM, DIM / SW1);
    k_silu<<<(INTER * B) / 256, 256>>>(buffer, bids);
    k_gemm<<<dim3(DIM / 128, SW2), 128>>>(w2, gT, w2P, DIM, INTER, INTER / SW2);
    k_final<<<(B * DIM) / 256, 256>>>(out);
}